// round 2
// baseline (speedup 1.0000x reference)
#include <cuda_runtime.h>

// rate_loss: x (32,64,128,128) fp32 -> scalar f32
//
//  k_clear : zero global histogram + sum accumulator
//  k_hist  : one pass; k = floor(5x); warp-aggregated (match_any) smem atomics
//            over a 256-bin hot window, global-atomic fallback for outliers
//  k_prep  : 1 block; vmin from lowest nonzero key, 200-bin shift, cumsum,
//            window-sum -> hist_add, diff -> g; store float2 {g, hist_add}
//  k_loss  : one pass (2x unrolled float4); piecewise-linear log2 accumulation
//  k_final : out = -sum / n

#define NBINS_MAX 200
#define BPU_I     5
#define GLEN      195   // NBINS_MAX - BPU
#define HLEN      196   // NBINS_MAX - BPU + 1
#define KBINS     1024  // global absolute-key histogram, keys [-512,511]
#define KOFF      512
#define WBINS     256   // smem hot window, keys [-128,127]
#define WOFF      128
#define HCOPIES   8     // one per warp
#define WSTRIDE   260   // 256 + 4 pad

__device__ unsigned int d_hist[KBINS];
__device__ double       d_sum;
__device__ float2       d_gh[GLEN];     // {g[i], hist_add[i]}
__device__ float        d_vminnew;

// ---------------------------------------------------------------- clear
__global__ void k_clear() {
    int t = blockIdx.x * blockDim.x + threadIdx.x;
    if (t < KBINS) d_hist[t] = 0u;
    if (t == 0) d_sum = 0.0;
}

// ---------------------------------------------------------------- histogram
__device__ __forceinline__ void hist_one(int k, unsigned int* __restrict__ h,
                                         int lane) {
    k = min(KOFF - 1, max(-KOFF, k));
    bool inw = (k >= -WOFF) & (k < WOFF);
    // out-of-window lanes get a unique sentinel so they form singleton groups
    int key = inw ? k : (2048 + lane);
    unsigned int am = __activemask();
    unsigned int m  = __match_any_sync(am, key);
    if (inw) {
        if (__ffs(m) - 1 == lane)                 // leader of equal-key group
            atomicAdd(&h[k + WOFF], __popc(m));
    } else {
        atomicAdd(&d_hist[k + KOFF], 1u);         // rare outlier path
    }
}

__global__ void __launch_bounds__(256) k_hist(const float* __restrict__ x,
                                              int n4, int n) {
    __shared__ unsigned int sh[HCOPIES * WSTRIDE];
    for (int i = threadIdx.x; i < HCOPIES * WSTRIDE; i += 256) sh[i] = 0u;
    __syncthreads();

    const int lane = threadIdx.x & 31;
    unsigned int* h = sh + (threadIdx.x >> 5) * WSTRIDE;
    const float4* x4 = (const float4*)x;
    const int stride = gridDim.x * 256;

    for (int idx = blockIdx.x * 256 + threadIdx.x; idx < n4; idx += stride) {
        float4 v = __ldg(&x4[idx]);
        int k0 = __float2int_rd(v.x * 5.0f);
        int k1 = __float2int_rd(v.y * 5.0f);
        int k2 = __float2int_rd(v.z * 5.0f);
        int k3 = __float2int_rd(v.w * 5.0f);
        hist_one(k0, h, lane);
        hist_one(k1, h, lane);
        hist_one(k2, h, lane);
        hist_one(k3, h, lane);
    }
    for (int idx = n4 * 4 + blockIdx.x * 256 + threadIdx.x; idx < n; idx += stride) {
        int k = __float2int_rd(__ldg(&x[idx]) * 5.0f);
        hist_one(k, h, lane);
    }
    __syncthreads();

    // merge 8 copies -> global (window bin b maps to global bin b - WOFF + KOFF)
    for (int b = threadIdx.x; b < WBINS; b += 256) {
        unsigned int s = 0;
        #pragma unroll
        for (int c = 0; c < HCOPIES; c++) s += sh[c * WSTRIDE + b];
        if (s) atomicAdd(&d_hist[b + (KOFF - WOFF)], s);
    }
}

// ---------------------------------------------------------------- prep (tiny)
__global__ void __launch_bounds__(256) k_prep(int n) {
    __shared__ unsigned int hist[KBINS];
    __shared__ int kmin_sh, kmax_sh;
    if (threadIdx.x == 0) { kmin_sh = KBINS; kmax_sh = -1; }
    for (int b = threadIdx.x; b < KBINS; b += 256) hist[b] = d_hist[b];
    __syncthreads();
    for (int b = threadIdx.x; b < KBINS; b += 256)
        if (hist[b]) { atomicMin(&kmin_sh, b); atomicMax(&kmax_sh, b); }
    __syncthreads();

    if (threadIdx.x == 0) {
        int kmin = kmin_sh - KOFF;                        // lowest key floor(5x)
        int jmin = (kmin >= 0) ? (kmin / 5) : -((-kmin + 4) / 5);  // floor(min)
        int vmin_i = jmin - 1;                            // vmin (integer)
        int shift = 5 * vmin_i;                           // hidx = k - 5*vmin

        float cnt[NBINS_MAX];
        for (int i = 0; i < NBINS_MAX; i++) cnt[i] = 0.0f;
        for (int b = kmin_sh; b <= kmax_sh; b++) {
            unsigned int c = hist[b];
            if (!c) continue;
            int t = (b - KOFF) - shift;
            t = min(NBINS_MAX - 1, max(0, t));
            cnt[t] += (float)c;
        }
        float inv_n = 1.0f / (float)n;
        float c_arr[NBINS_MAX + 1];
        c_arr[0] = 0.0f;
        for (int i = 0; i < NBINS_MAX; i++)
            c_arr[i + 1] = c_arr[i] + cnt[i] * inv_n;
        float hist_add[HLEN];
        for (int i = 0; i < HLEN; i++)
            hist_add[i] = c_arr[i + BPU_I] - c_arr[i];
        for (int i = 0; i < GLEN; i++) {
            float g = (hist_add[i + 1] - hist_add[i]) * 5.0f;
            d_gh[i] = make_float2(g, hist_add[i]);
        }
        d_vminnew = (float)vmin_i + 0.5f;
    }
}

// ---------------------------------------------------------------- loss
__device__ __forceinline__ float eval_one(float xv, float vmn,
                                          const float2* __restrict__ gh) {
    float t = (xv - vmn) * 5.0f;
    float f = floorf(t);
    f = fminf(fmaxf(f, 0.0f), (float)(GLEN - 1));
    int i = (int)f;
    float left = fmaf(f, 0.2f, vmn);
    float2 p = gh[i];
    float nl = fmaf(xv - left, p.x, p.y) + 1e-8f;
    return __log2f(nl);
}

__global__ void __launch_bounds__(256) k_loss(const float* __restrict__ x,
                                              int n4, int n) {
    __shared__ float2 gh[GLEN];
    __shared__ float wsum[8];
    for (int i = threadIdx.x; i < GLEN; i += 256) gh[i] = d_gh[i];
    float vmn = d_vminnew;
    __syncthreads();

    const float4* x4 = (const float4*)x;
    const int st = gridDim.x * 256;
    float acc = 0.0f;

    int idx = blockIdx.x * 256 + threadIdx.x;
    // 2x unrolled: two independent float4 loads per iteration
    for (; idx + st < n4; idx += 2 * st) {
        float4 a = __ldg(&x4[idx]);
        float4 b = __ldg(&x4[idx + st]);
        acc += eval_one(a.x, vmn, gh);
        acc += eval_one(a.y, vmn, gh);
        acc += eval_one(a.z, vmn, gh);
        acc += eval_one(a.w, vmn, gh);
        acc += eval_one(b.x, vmn, gh);
        acc += eval_one(b.y, vmn, gh);
        acc += eval_one(b.z, vmn, gh);
        acc += eval_one(b.w, vmn, gh);
    }
    for (; idx < n4; idx += st) {
        float4 a = __ldg(&x4[idx]);
        acc += eval_one(a.x, vmn, gh);
        acc += eval_one(a.y, vmn, gh);
        acc += eval_one(a.z, vmn, gh);
        acc += eval_one(a.w, vmn, gh);
    }
    for (int j = n4 * 4 + blockIdx.x * 256 + threadIdx.x; j < n; j += st)
        acc += eval_one(__ldg(&x[j]), vmn, gh);

    #pragma unroll
    for (int o = 16; o > 0; o >>= 1)
        acc += __shfl_down_sync(0xffffffffu, acc, o);
    int wid = threadIdx.x >> 5, lid = threadIdx.x & 31;
    if (lid == 0) wsum[wid] = acc;
    __syncthreads();
    if (wid == 0) {
        float s = (lid < 8) ? wsum[lid] : 0.0f;
        #pragma unroll
        for (int o = 4; o > 0; o >>= 1)
            s += __shfl_down_sync(0xffffffffu, s, o);
        if (lid == 0) atomicAdd(&d_sum, (double)s);
    }
}

// ---------------------------------------------------------------- finalize
__global__ void k_final(float* __restrict__ out, int n) {
    out[0] = (float)(-d_sum / (double)n);
}

// ---------------------------------------------------------------- launch
extern "C" void kernel_launch(void* const* d_in, const int* in_sizes, int n_in,
                              void* d_out, int out_size) {
    const float* x = (const float*)d_in[0];
    int n  = in_sizes[0];
    int n4 = n >> 2;
    const int GRID = 1184;  // 8 per SM * 148

    k_clear<<<4, 256>>>();
    k_hist<<<GRID, 256>>>(x, n4, n);
    k_prep<<<1, 256>>>(n);
    k_loss<<<GRID, 256>>>(x, n4, n);
    k_final<<<1, 1>>>((float*)d_out, n);
}

// round 3
// speedup vs baseline: 1.8429x; 1.8429x over previous
#include <cuda_runtime.h>

// rate_loss: x (32,64,128,128) fp32 -> scalar f32
//
//  k_clear : zero global histogram + sum accumulator
//  k_hist  : one pass; k = floor(5x); ATOMIC-FREE per-thread private counters
//            (two u16 bins packed per u32, conflict-free smem layout),
//            64-bin hot window, global-atomic fallback for outliers
//  k_prep  : 1 block; vmin from lowest nonzero key, 200-bin shift, cumsum,
//            window-sum -> hist_add, diff -> g; store float2 {g, hist_add}
//  k_loss  : one pass (4x float4 front-batched); piecewise-linear log2 accum
//  k_final : out = -sum / n

#define NBINS_MAX 200
#define BPU_I     5
#define GLEN      195   // NBINS_MAX - BPU
#define HLEN      196   // NBINS_MAX - BPU + 1
#define KBINS     1024  // global absolute-key histogram, keys [-512,511]
#define KOFF      512
#define WBINS     64    // hot window, keys [-32,32)  (|x| < 6.4)
#define WOFF      32
#define NPAIR     32    // WBINS/2 packed pairs

__device__ unsigned int d_hist[KBINS];
__device__ double       d_sum;
__device__ float2       d_gh[GLEN];     // {g[i], hist_add[i]}
__device__ float        d_vminnew;

// ---------------------------------------------------------------- clear
__global__ void k_clear() {
    int t = blockIdx.x * blockDim.x + threadIdx.x;
    if (t < KBINS) d_hist[t] = 0u;
    if (t == 0) d_sum = 0.0;
}

// ---------------------------------------------------------------- histogram
// sh layout: word[pair][tid], pair = bin & 31; low u16 = bin<32, high = bin>=32.
// Word index = pair*256 + tid -> bank = tid & 31 : conflict-free always.
__device__ __forceinline__ void hist_one(float v, unsigned int* __restrict__ sh,
                                         int tid) {
    int k = __float2int_rd(v * 5.0f);
    if (k >= -WOFF && k < WOFF) {
        int b = k + WOFF;                       // 0..63
        unsigned int inc = (b & 32) ? 65536u : 1u;
        sh[(b & 31) * 256 + tid] += inc;        // LDS + IADD + STS, no atomic
    } else {
        k = min(KOFF - 1, max(-KOFF, k));
        atomicAdd(&d_hist[k + KOFF], 1u);       // vanishingly rare
    }
}

__global__ void __launch_bounds__(256) k_hist(const float* __restrict__ x,
                                              int n4, int n) {
    __shared__ unsigned int sh[NPAIR * 256];    // 32 KB
    const int tid = threadIdx.x;
    for (int i = tid; i < NPAIR * 256; i += 256) sh[i] = 0u;
    __syncthreads();

    const float4* x4 = (const float4*)x;
    const int st = gridDim.x * 256;

    int idx = blockIdx.x * 256 + tid;
    for (; idx + st < n4; idx += 2 * st) {      // 2 front-batched float4 loads
        float4 a = __ldg(&x4[idx]);
        float4 b = __ldg(&x4[idx + st]);
        hist_one(a.x, sh, tid); hist_one(a.y, sh, tid);
        hist_one(a.z, sh, tid); hist_one(a.w, sh, tid);
        hist_one(b.x, sh, tid); hist_one(b.y, sh, tid);
        hist_one(b.z, sh, tid); hist_one(b.w, sh, tid);
    }
    for (; idx < n4; idx += st) {
        float4 a = __ldg(&x4[idx]);
        hist_one(a.x, sh, tid); hist_one(a.y, sh, tid);
        hist_one(a.z, sh, tid); hist_one(a.w, sh, tid);
    }
    for (int j = n4 * 4 + blockIdx.x * 256 + tid; j < n; j += st)
        hist_one(__ldg(&x[j]), sh, tid);
    __syncthreads();

    // merge: warp w reduces bins [w*8, w*8+8); lane-strided columns (bank-free)
    const int wid = tid >> 5, lane = tid & 31;
    for (int b = wid * 8; b < wid * 8 + 8; b++) {
        const unsigned int* col = sh + (b & 31) * 256;
        int shift = (b & 32) ? 16 : 0;
        unsigned int s = 0;
        #pragma unroll
        for (int c = 0; c < 8; c++)
            s += (col[lane + 32 * c] >> shift) & 0xFFFFu;
        #pragma unroll
        for (int o = 16; o > 0; o >>= 1)
            s += __shfl_down_sync(0xffffffffu, s, o);
        if (lane == 0 && s)
            atomicAdd(&d_hist[b - WOFF + KOFF], s);
    }
}

// ---------------------------------------------------------------- prep (tiny)
__global__ void __launch_bounds__(256) k_prep(int n) {
    __shared__ unsigned int hist[KBINS];
    __shared__ int kmin_sh, kmax_sh;
    if (threadIdx.x == 0) { kmin_sh = KBINS; kmax_sh = -1; }
    for (int b = threadIdx.x; b < KBINS; b += 256) hist[b] = d_hist[b];
    __syncthreads();
    for (int b = threadIdx.x; b < KBINS; b += 256)
        if (hist[b]) { atomicMin(&kmin_sh, b); atomicMax(&kmax_sh, b); }
    __syncthreads();

    if (threadIdx.x == 0) {
        int kmin = kmin_sh - KOFF;                        // lowest key floor(5x)
        int jmin = (kmin >= 0) ? (kmin / 5) : -((-kmin + 4) / 5);  // floor(min)
        int vmin_i = jmin - 1;                            // vmin (integer)
        int shift = 5 * vmin_i;                           // hidx = k - 5*vmin

        float cnt[NBINS_MAX];
        for (int i = 0; i < NBINS_MAX; i++) cnt[i] = 0.0f;
        for (int b = kmin_sh; b <= kmax_sh; b++) {
            unsigned int c = hist[b];
            if (!c) continue;
            int t = (b - KOFF) - shift;
            t = min(NBINS_MAX - 1, max(0, t));
            cnt[t] += (float)c;
        }
        float inv_n = 1.0f / (float)n;
        float c_arr[NBINS_MAX + 1];
        c_arr[0] = 0.0f;
        for (int i = 0; i < NBINS_MAX; i++)
            c_arr[i + 1] = c_arr[i] + cnt[i] * inv_n;
        float hist_add[HLEN];
        for (int i = 0; i < HLEN; i++)
            hist_add[i] = c_arr[i + BPU_I] - c_arr[i];
        for (int i = 0; i < GLEN; i++) {
            float g = (hist_add[i + 1] - hist_add[i]) * 5.0f;
            d_gh[i] = make_float2(g, hist_add[i]);
        }
        d_vminnew = (float)vmin_i + 0.5f;
    }
}

// ---------------------------------------------------------------- loss
__device__ __forceinline__ float eval_one(float xv, float vmn,
                                          const float2* __restrict__ gh) {
    float t = (xv - vmn) * 5.0f;
    float f = floorf(t);
    f = fminf(fmaxf(f, 0.0f), (float)(GLEN - 1));
    int i = (int)f;
    float left = fmaf(f, 0.2f, vmn);
    float2 p = gh[i];
    float nl = fmaf(xv - left, p.x, p.y) + 1e-8f;
    return __log2f(nl);
}

__global__ void __launch_bounds__(256) k_loss(const float* __restrict__ x,
                                              int n4, int n) {
    __shared__ float2 gh[GLEN];
    __shared__ float wsum[8];
    for (int i = threadIdx.x; i < GLEN; i += 256) gh[i] = d_gh[i];
    float vmn = d_vminnew;
    __syncthreads();

    const float4* x4 = (const float4*)x;
    const int st = gridDim.x * 256;
    float acc = 0.0f;

    int idx = blockIdx.x * 256 + threadIdx.x;
    // 4 front-batched independent float4 loads per iteration
    for (; idx + 3 * st < n4; idx += 4 * st) {
        float4 a = __ldg(&x4[idx]);
        float4 b = __ldg(&x4[idx + st]);
        float4 c = __ldg(&x4[idx + 2 * st]);
        float4 d = __ldg(&x4[idx + 3 * st]);
        acc += eval_one(a.x, vmn, gh); acc += eval_one(a.y, vmn, gh);
        acc += eval_one(a.z, vmn, gh); acc += eval_one(a.w, vmn, gh);
        acc += eval_one(b.x, vmn, gh); acc += eval_one(b.y, vmn, gh);
        acc += eval_one(b.z, vmn, gh); acc += eval_one(b.w, vmn, gh);
        acc += eval_one(c.x, vmn, gh); acc += eval_one(c.y, vmn, gh);
        acc += eval_one(c.z, vmn, gh); acc += eval_one(c.w, vmn, gh);
        acc += eval_one(d.x, vmn, gh); acc += eval_one(d.y, vmn, gh);
        acc += eval_one(d.z, vmn, gh); acc += eval_one(d.w, vmn, gh);
    }
    for (; idx < n4; idx += st) {
        float4 a = __ldg(&x4[idx]);
        acc += eval_one(a.x, vmn, gh); acc += eval_one(a.y, vmn, gh);
        acc += eval_one(a.z, vmn, gh); acc += eval_one(a.w, vmn, gh);
    }
    for (int j = n4 * 4 + blockIdx.x * 256 + threadIdx.x; j < n; j += st)
        acc += eval_one(__ldg(&x[j]), vmn, gh);

    #pragma unroll
    for (int o = 16; o > 0; o >>= 1)
        acc += __shfl_down_sync(0xffffffffu, acc, o);
    int wid = threadIdx.x >> 5, lid = threadIdx.x & 31;
    if (lid == 0) wsum[wid] = acc;
    __syncthreads();
    if (wid == 0) {
        float s = (lid < 8) ? wsum[lid] : 0.0f;
        #pragma unroll
        for (int o = 4; o > 0; o >>= 1)
            s += __shfl_down_sync(0xffffffffu, s, o);
        if (lid == 0) atomicAdd(&d_sum, (double)s);
    }
}

// ---------------------------------------------------------------- finalize
__global__ void k_final(float* __restrict__ out, int n) {
    out[0] = (float)(-d_sum / (double)n);
}

// ---------------------------------------------------------------- launch
extern "C" void kernel_launch(void* const* d_in, const int* in_sizes, int n_in,
                              void* d_out, int out_size) {
    const float* x = (const float*)d_in[0];
    int n  = in_sizes[0];
    int n4 = n >> 2;
    const int GRID_H = 1036;  // 7 per SM * 148 (32KB smem/block)
    const int GRID_L = 1184;  // 8 per SM * 148

    k_clear<<<4, 256>>>();
    k_hist<<<GRID_H, 256>>>(x, n4, n);
    k_prep<<<1, 256>>>(n);
    k_loss<<<GRID_L, 256>>>(x, n4, n);
    k_final<<<1, 1>>>((float*)d_out, n);
}